// round 2
// baseline (speedup 1.0000x reference)
#include <cuda_runtime.h>
#include <math.h>

// LIF cell scan: v = v*sigmoid(decay)*(1-z) + x_t ; z = (v - 0.5 > 0)
// Shapes: x [B,T,H] f32, decay [H] f32, v0 [B,H] f32, z0 [B,H] f32
// Output: spikes [B,T,H] f32.  B=512, T=512, H=256.
//
// One thread per (b,h) chain, sequential over T. Pure HBM streaming:
// 256MB read + 256MB write -> ~70us floor at ~7.5TB/s.

#define B_DIM 512
#define T_DIM 512
#define H_DIM 256
#define UNROLL 16

__global__ __launch_bounds__(H_DIM, 4)
void lif_scan_kernel(const float* __restrict__ x,
                     const float* __restrict__ decay,
                     const float* __restrict__ v0,
                     const float* __restrict__ z0,
                     float* __restrict__ out)
{
    const int h = threadIdx.x;      // 0..255, contiguous in warp -> coalesced
    const int b = blockIdx.x;       // 0..511

    // sigmoid(decay[h]) once per thread, correctly rounded via fp64
    const float d = (float)(1.0 / (1.0 + exp(-(double)decay[h])));

    const int bh = b * H_DIM + h;
    float v = v0[bh];
    float z = z0[bh];

    const size_t base = (size_t)b * T_DIM * H_DIM + h;
    const float* __restrict__ xp = x + base;
    float* __restrict__ op = out + base;

    #pragma unroll 1
    for (int t = 0; t < T_DIM; t += UNROLL) {
        // Front-batched loads: 16 independent LDGs in flight per thread
        float xv[UNROLL];
        #pragma unroll
        for (int i = 0; i < UNROLL; i++) {
            xv[i] = __ldcs(xp + (size_t)(t + i) * H_DIM);
        }

        // Serial recurrence over this chunk (register-resident).
        // (1 - z) is exactly 0.0f or 1.0f, so rounding matches the reference
        // regardless of mul/fma association.
        float ov[UNROLL];
        #pragma unroll
        for (int i = 0; i < UNROLL; i++) {
            v = v * d * (1.0f - z) + xv[i];
            z = (v > 0.5f) ? 1.0f : 0.0f;
            ov[i] = z;
        }

        // Streaming stores (touch-once output)
        #pragma unroll
        for (int i = 0; i < UNROLL; i++) {
            __stcs(op + (size_t)(t + i) * H_DIM, ov[i]);
        }
    }
}

extern "C" void kernel_launch(void* const* d_in, const int* in_sizes, int n_in,
                              void* d_out, int out_size)
{
    // Identify inputs BY SIZE, not by position, so a metadata ordering that
    // differs from the reference dict order cannot cause OOB access.
    //   x:     B*T*H = 67,108,864
    //   decay: H     = 256
    //   v0,z0: B*H   = 131,072  (v0 first in every plausible ordering; both
    //                            are zeros at runtime so a swap is harmless)
    const float* x = 0;
    const float* decay = 0;
    const float* v0 = 0;
    const float* z0 = 0;

    const long long n_x  = (long long)B_DIM * T_DIM * H_DIM;
    const long long n_bh = (long long)B_DIM * H_DIM;

    for (int i = 0; i < n_in; i++) {
        long long n = in_sizes[i];
        if (n == n_x) {
            x = (const float*)d_in[i];
        } else if (n == H_DIM) {
            decay = (const float*)d_in[i];
        } else if (n == n_bh) {
            if (!v0) v0 = (const float*)d_in[i];
            else     z0 = (const float*)d_in[i];
        }
    }
    if (!x || !decay || !v0 || !z0) return;  // shape mismatch: do nothing safely

    float* out = (float*)d_out;  // [B,T,H]

    lif_scan_kernel<<<B_DIM, H_DIM>>>(x, decay, v0, z0, out);
}